// round 1
// baseline (speedup 1.0000x reference)
#include <cuda_runtime.h>
#include <math.h>

#define BATCH 2
#define SEQ   2048
#define EMB   1024
#define NH    16
#define HD    64
#define DFF   4096
#define ROWS  (BATCH*SEQ)   // 4096

// ---------------- scratch (device globals; no allocation) ----------------
__device__ float g_xn  [ROWS * EMB];        // LN1 output
__device__ float g_kqv [ROWS * 3 * EMB];    // kqv projection
__device__ float g_attn[ROWS * EMB];        // attention output
__device__ float g_h   [ROWS * EMB];        // LN2 output
__device__ float g_mid [ROWS * DFF];        // FFN mid

// ---------------- LayerNorm (optionally fused residual add) ----------------
// grid = ROWS, block = 256 (each thread handles one float4 of the 1024-wide row)
template <bool FUSE_ADD>
__global__ __launch_bounds__(256) void ln_kernel(
    const float* __restrict__ x,
    const float* __restrict__ addend,     // attn output (if FUSE_ADD)
    float*       __restrict__ resid_out,  // x1 output (if FUSE_ADD)
    const float* __restrict__ gamma,
    const float* __restrict__ beta,
    float*       __restrict__ out)
{
    const int row = blockIdx.x;
    const int t   = threadIdx.x;
    const size_t base = (size_t)row * EMB;

    float4 v = *(const float4*)(x + base + t * 4);
    if (FUSE_ADD) {
        float4 a = *(const float4*)(addend + base + t * 4);
        v.x += a.x; v.y += a.y; v.z += a.z; v.w += a.w;
        *(float4*)(resid_out + base + t * 4) = v;
    }
    float s  = v.x + v.y + v.z + v.w;
    float ss = v.x*v.x + v.y*v.y + v.z*v.z + v.w*v.w;

    #pragma unroll
    for (int off = 16; off; off >>= 1) {
        s  += __shfl_down_sync(0xffffffffu, s,  off);
        ss += __shfl_down_sync(0xffffffffu, ss, off);
    }
    __shared__ float rs[8], rss[8];
    const int warp = t >> 5, lane = t & 31;
    if (lane == 0) { rs[warp] = s; rss[warp] = ss; }
    __syncthreads();
    if (t == 0) {
        float a = 0.f, b = 0.f;
        #pragma unroll
        for (int i = 0; i < 8; i++) { a += rs[i]; b += rss[i]; }
        rs[0] = a; rss[0] = b;
    }
    __syncthreads();
    const float mu  = rs[0] * (1.0f / EMB);
    const float var = rss[0] * (1.0f / EMB) - mu * mu;
    const float inv = rsqrtf(var + 1e-5f);

    float4 g = *(const float4*)(gamma + t * 4);
    float4 b4 = *(const float4*)(beta + t * 4);
    float4 o;
    o.x = (v.x - mu) * inv * g.x + b4.x;
    o.y = (v.y - mu) * inv * g.y + b4.y;
    o.z = (v.z - mu) * inv * g.z + b4.z;
    o.w = (v.w - mu) * inv * g.w + b4.w;
    *(float4*)(out + base + t * 4) = o;
}

// ---------------- SGEMM: C[M,N] = A[M,K] @ B[K,N] (+bias,+relu,+resid) ----
// BM=BN=128, BK=16, TM=TN=8, 256 threads. M,N multiples of 128; K of 16.
#define BM 128
#define BN 128
#define BK 16
#define TM 8
#define TN 8

template <bool DO_BIAS, bool DO_RELU, bool DO_RESID>
__global__ __launch_bounds__(256) void sgemm_kernel(
    int M, int N, int K,
    const float* __restrict__ A,
    const float* __restrict__ B,
    const float* __restrict__ bias,
    const float* __restrict__ resid,
    float*       __restrict__ C)
{
    __shared__ float As[BK][BM + 4];  // padded: kills store bank conflicts
    __shared__ float Bs[BK][BN];

    const int tid  = threadIdx.x;
    const int cRow = blockIdx.y;
    const int cCol = blockIdx.x;

    const float* Ag = A + (size_t)cRow * BM * K;
    const float* Bg = B + (size_t)cCol * BN;

    const int aRow = tid >> 2;          // 0..63
    const int aCol = (tid & 3) << 2;    // 0,4,8,12
    const int bRow = tid >> 5;          // 0..7
    const int bCol = (tid & 31) << 2;   // 0..124

    const int threadRow = tid >> 4;     // 0..15
    const int threadCol = tid & 15;     // 0..15

    float acc[TM][TN] = {};

    for (int k0 = 0; k0 < K; k0 += BK) {
        #pragma unroll
        for (int r = 0; r < BM; r += 64) {
            float4 v = *(const float4*)&Ag[(size_t)(aRow + r) * K + k0 + aCol];
            As[aCol + 0][aRow + r] = v.x;
            As[aCol + 1][aRow + r] = v.y;
            As[aCol + 2][aRow + r] = v.z;
            As[aCol + 3][aRow + r] = v.w;
        }
        #pragma unroll
        for (int r = 0; r < BK; r += 8) {
            *(float4*)&Bs[bRow + r][bCol] =
                *(const float4*)&Bg[(size_t)(k0 + bRow + r) * N + bCol];
        }
        __syncthreads();

        #pragma unroll
        for (int k = 0; k < BK; k++) {
            float regM[TM], regN[TN];
            *(float4*)&regM[0] = *(float4*)&As[k][threadRow * TM + 0];
            *(float4*)&regM[4] = *(float4*)&As[k][threadRow * TM + 4];
            *(float4*)&regN[0] = *(float4*)&Bs[k][threadCol * TN + 0];
            *(float4*)&regN[4] = *(float4*)&Bs[k][threadCol * TN + 4];
            #pragma unroll
            for (int i = 0; i < TM; i++)
                #pragma unroll
                for (int j = 0; j < TN; j++)
                    acc[i][j] += regM[i] * regN[j];
        }
        __syncthreads();
    }

    // epilogue
    #pragma unroll
    for (int i = 0; i < TM; i++) {
        const size_t row = (size_t)cRow * BM + threadRow * TM + i;
        #pragma unroll
        for (int j = 0; j < TN; j += 4) {
            const int col = cCol * BN + threadCol * TN + j;
            float4 v = make_float4(acc[i][j], acc[i][j+1], acc[i][j+2], acc[i][j+3]);
            if (DO_BIAS) {
                float4 b = *(const float4*)&bias[col];
                v.x += b.x; v.y += b.y; v.z += b.z; v.w += b.w;
            }
            if (DO_RELU) {
                v.x = fmaxf(v.x, 0.f); v.y = fmaxf(v.y, 0.f);
                v.z = fmaxf(v.z, 0.f); v.w = fmaxf(v.w, 0.f);
            }
            if (DO_RESID) {
                float4 r = *(const float4*)&resid[row * N + col];
                v.x += r.x; v.y += r.y; v.z += r.z; v.w += r.w;
            }
            *(float4*)&C[row * N + col] = v;
        }
    }
}

// ---------------- Flash attention with ALiBi (causal) ---------------------
// grid = (SEQ/128, NH, BATCH), block = 128 (one thread per query row)
// kqv row layout: [ k(0..1023) | q(1024..2047) | v(2048..3071) ]
__global__ __launch_bounds__(128) void attn_kernel(
    const float* __restrict__ kqv, float* __restrict__ out)
{
    const int b = blockIdx.z;
    const int h = blockIdx.y;
    const int q = blockIdx.x * 128 + threadIdx.x;
    const int tid = threadIdx.x;
    const float slope = exp2f(-0.5f * (float)(h + 1));  // 1/x^(h+1), x=2^(8/16)

    __shared__ float Ks[64][64];
    __shared__ float Vs[64][64];

    // load this thread's query row into registers
    float4 qr[16];
    {
        const float* qp = kqv + ((size_t)(b * SEQ + q)) * (3 * EMB) + EMB + h * HD;
        #pragma unroll
        for (int i = 0; i < 16; i++) qr[i] = *(const float4*)(qp + i * 4);
    }

    float4 o[16];
    #pragma unroll
    for (int i = 0; i < 16; i++) o[i] = make_float4(0.f, 0.f, 0.f, 0.f);
    float m = -INFINITY, l = 0.f;

    const int ntiles = blockIdx.x * 2 + 2;  // tiles of 64 keys up to causal edge
    for (int t = 0; t < ntiles; t++) {
        __syncthreads();
        // cooperative K/V tile load: 64 rows x 64 cols, float4
        #pragma unroll
        for (int i = 0; i < 8; i++) {
            const int idx = tid + i * 128;         // 0..1023
            const int j   = idx >> 4;              // key row 0..63
            const int d4  = idx & 15;              // float4 column
            const float* kp = kqv + ((size_t)(b * SEQ + t * 64 + j)) * (3 * EMB) + h * HD;
            *(float4*)&Ks[j][d4 * 4] = *(const float4*)(kp + d4 * 4);
            *(float4*)&Vs[j][d4 * 4] = *(const float4*)(kp + 2 * EMB + d4 * 4);
        }
        __syncthreads();

        const int jmax = min(64, q - t * 64 + 1);  // causal: key <= q
        for (int j = 0; j < jmax; j++) {
            float s = 0.f;
            #pragma unroll
            for (int d4 = 0; d4 < 16; d4++) {
                float4 kv = *(float4*)&Ks[j][d4 * 4];
                s += qr[d4].x * kv.x + qr[d4].y * kv.y
                   + qr[d4].z * kv.z + qr[d4].w * kv.w;
            }
            const int key = t * 64 + j;
            s = s * (1.0f / 32.0f) + slope * (float)(key - q);

            float p;
            if (s > m) {   // rare path: rescale accumulator
                const float c = __expf(m - s);  // expf(-inf)=0 handles first key
                l *= c;
                #pragma unroll
                for (int d4 = 0; d4 < 16; d4++) {
                    o[d4].x *= c; o[d4].y *= c; o[d4].z *= c; o[d4].w *= c;
                }
                m = s; p = 1.f;
            } else {
                p = __expf(s - m);
            }
            l += p;
            #pragma unroll
            for (int d4 = 0; d4 < 16; d4++) {
                float4 vv = *(float4*)&Vs[j][d4 * 4];
                o[d4].x += p * vv.x; o[d4].y += p * vv.y;
                o[d4].z += p * vv.z; o[d4].w += p * vv.w;
            }
        }
    }

    const float inv = 1.0f / l;
    float* op = out + ((size_t)(b * SEQ + q)) * EMB + h * HD;
    #pragma unroll
    for (int d4 = 0; d4 < 16; d4++) {
        float4 v = o[d4];
        v.x *= inv; v.y *= inv; v.z *= inv; v.w *= inv;
        *(float4*)(op + d4 * 4) = v;
    }
}

// ---------------- driver ---------------------------------------------------
extern "C" void kernel_launch(void* const* d_in, const int* in_sizes, int n_in,
                              void* d_out, int out_size)
{
    const float* x     = (const float*)d_in[0];
    const float* w_kqv = (const float*)d_in[1];
    const float* ln1_g = (const float*)d_in[2];
    const float* ln1_b = (const float*)d_in[3];
    const float* ln2_g = (const float*)d_in[4];
    const float* ln2_b = (const float*)d_in[5];
    const float* w1    = (const float*)d_in[6];
    const float* b1    = (const float*)d_in[7];
    const float* w2    = (const float*)d_in[8];
    const float* b2    = (const float*)d_in[9];
    float* out = (float*)d_out;

    float* xn; float* kqv; float* attn; float* hbuf; float* mid;
    cudaGetSymbolAddress((void**)&xn,   g_xn);
    cudaGetSymbolAddress((void**)&kqv,  g_kqv);
    cudaGetSymbolAddress((void**)&attn, g_attn);
    cudaGetSymbolAddress((void**)&hbuf, g_h);
    cudaGetSymbolAddress((void**)&mid,  g_mid);

    // 1) LN1: xn = LN(x)
    ln_kernel<false><<<ROWS, 256>>>(x, nullptr, nullptr, ln1_g, ln1_b, xn);

    // 2) kqv = xn @ w_kqv   [4096 x 3072]
    {
        dim3 grid(3 * EMB / BN, ROWS / BM);
        sgemm_kernel<false, false, false><<<grid, 256>>>(
            ROWS, 3 * EMB, EMB, xn, w_kqv, nullptr, nullptr, kqv);
    }

    // 3) attention -> attn
    {
        dim3 grid(SEQ / 128, NH, BATCH);
        attn_kernel<<<grid, 128>>>(kqv, attn);
    }

    // 4) x1 = x + attn (-> d_out), h = LN2(x1)
    ln_kernel<true><<<ROWS, 256>>>(x, attn, out, ln2_g, ln2_b, hbuf);

    // 5) mid = relu(h @ w1 + b1)   [4096 x 4096]
    {
        dim3 grid(DFF / BN, ROWS / BM);
        sgemm_kernel<true, true, false><<<grid, 256>>>(
            ROWS, DFF, EMB, hbuf, w1, b1, nullptr, mid);
    }

    // 6) out = x1 + mid @ w2 + b2   [4096 x 1024], in-place residual on d_out
    {
        dim3 grid(EMB / BN, ROWS / BM);
        sgemm_kernel<true, false, true><<<grid, 256>>>(
            ROWS, EMB, DFF, mid, w2, b2, out, out);
    }
    (void)in_sizes; (void)n_in; (void)out_size;
}

// round 3
// speedup vs baseline: 1.9576x; 1.9576x over previous
#include <cuda_runtime.h>
#include <cuda.h>
#include <stdint.h>
#include <math.h>

#define BATCH 2
#define SEQ   2048
#define EMB   1024
#define NH    16
#define HD    64
#define DFF   4096
#define ROWS  (BATCH*SEQ)   // 4096

// ---------------- scratch (device globals; no allocation) ----------------
__device__ __align__(128) float g_xn   [ROWS * EMB];
__device__ __align__(128) float g_kqv  [ROWS * 3 * EMB];
__device__ __align__(128) float g_attn [ROWS * EMB];
__device__ __align__(128) float g_h    [ROWS * EMB];
__device__ __align__(128) float g_mid  [ROWS * DFF];
__device__ __align__(128) float g_wkqvT[3 * EMB * EMB];   // [3E, E]  (N,K)
__device__ __align__(128) float g_w1T  [DFF * EMB];       // [DFF, E]
__device__ __align__(128) float g_w2T  [EMB * DFF];       // [E, DFF]

// ====================== PTX helpers ========================================
__device__ __forceinline__ uint32_t smem_u32(const void* p) {
    uint32_t a;
    asm("{ .reg .u64 t; cvta.to.shared.u64 t, %1; cvt.u32.u64 %0, t; }"
        : "=r"(a) : "l"(p));
    return a;
}

#define MBARRIER_INIT(addr, cnt) \
    asm volatile("mbarrier.init.shared.b64 [%0], %1;" :: "r"((uint32_t)(addr)), "r"((uint32_t)(cnt)) : "memory")

#define MBARRIER_ARRIVE(addr) \
    asm volatile("mbarrier.arrive.shared.b64 _, [%0];" :: "r"((uint32_t)(addr)) : "memory")

#define MBARRIER_EXPECT_TX(addr, bytes) \
    asm volatile("mbarrier.arrive.expect_tx.shared.b64 _, [%0], %1;" :: "r"((uint32_t)(addr)), "r"((uint32_t)(bytes)) : "memory")

#define MBARRIER_WAIT_PARITY(addr, ph) do { \
    uint32_t _m = (uint32_t)(addr); uint32_t _p = (uint32_t)(ph); uint32_t _d; \
    asm volatile("{\n\t.reg .pred p;\n\t" \
        "mbarrier.try_wait.parity.acquire.cta.shared::cta.b64 p, [%1], %2;\n\t" \
        "selp.b32 %0, 1, 0, p;\n\t}" : "=r"(_d) : "r"(_m), "r"(_p) : "memory"); \
    if (!_d) { \
        asm volatile("{\n\t.reg .pred P1;\n\t" \
            "WL_%=:\n\t" \
            "mbarrier.try_wait.parity.acquire.cta.shared::cta.b64 P1, [%0], %1, 0x989680;\n\t" \
            "@P1 bra.uni WD_%=;\n\t" \
            "bra.uni WL_%=;\n\t" \
            "WD_%=:\n\t}" :: "r"(_m), "r"(_p) : "memory"); \
    } \
} while (0)

#define MBARRIER_WAIT_PARITY_RELAXED(addr, ph) do { \
    uint32_t _m = (uint32_t)(addr); uint32_t _p = (uint32_t)(ph); uint32_t _d; \
    asm volatile("{\n\t.reg .pred p;\n\t" \
        "mbarrier.try_wait.parity.relaxed.cta.shared::cta.b64 p, [%1], %2, 0x989680;\n\t" \
        "selp.b32 %0, 1, 0, p;\n\t}" : "=r"(_d) : "r"(_m), "r"(_p) : "memory"); \
    if (!_d) { \
        asm volatile("{\n\t.reg .pred P1;\n\t" \
            "WL_%=:\n\t" \
            "mbarrier.try_wait.parity.relaxed.cta.shared::cta.b64 P1, [%0], %1, 0x989680;\n\t" \
            "@P1 bra.uni WD_%=;\n\t" \
            "bra.uni WL_%=;\n\t" \
            "WD_%=:\n\t}" :: "r"(_m), "r"(_p) : "memory"); \
    } \
} while (0)

// 2D TMA load into shared::cta
#define TMA2D(smemaddr, mapptr, cx, cy, mbar) \
    asm volatile("cp.async.bulk.tensor.2d.shared::cta.global.tile.mbarrier::complete_tx::bytes " \
        "[%0], [%1, {%2, %3}], [%4];" \
        :: "r"((uint32_t)(smemaddr)), "l"(mapptr), "r"((int)(cx)), "r"((int)(cy)), \
           "r"((uint32_t)(mbar)) : "memory")

__device__ __forceinline__ float lds_f32(uint32_t addr) {
    float v;
    asm volatile("ld.shared.f32 %0, [%1];" : "=f"(v) : "r"(addr));
    return v;
}

// mma.sync m16n8k8 tf32 (legacy tensor-core path; valid PTX for sm_103 generic)
__device__ __forceinline__ void mma_tf32(float* c, const float* a, const float* b) {
    asm volatile(
        "mma.sync.aligned.m16n8k8.row.col.f32.tf32.tf32.f32 "
        "{%0,%1,%2,%3}, {%4,%5,%6,%7}, {%8,%9}, {%0,%1,%2,%3};"
        : "+f"(c[0]), "+f"(c[1]), "+f"(c[2]), "+f"(c[3])
        : "r"(__float_as_uint(a[0])), "r"(__float_as_uint(a[1])),
          "r"(__float_as_uint(a[2])), "r"(__float_as_uint(a[3])),
          "r"(__float_as_uint(b[0])), "r"(__float_as_uint(b[1])));
}

// ====================== GEMM (TMA + mma.sync tf32) =========================
// C[M,N] = A[M,K] @ Bt[N,K]^T ; tiles 128x128, BK=32 fp32 (=128B SW128 rows)
#define GBM 128
#define GBN 128
#define GBK 32
#define GS  4
#define STAGE_A_BYTES (GBM * GBK * 4)                 // 16384
#define STAGE_B_BYTES (GBN * GBK * 4)                 // 16384
#define STAGE_BYTES   (STAGE_A_BYTES + STAGE_B_BYTES) // 32768
#define SMEM_A_OFF(s) (1024 + (s) * STAGE_BYTES)
#define SMEM_B_OFF(s) (SMEM_A_OFF(s) + STAGE_A_BYTES)
#define GEMM_SMEM_TOTAL (1024 + GS * STAGE_BYTES)     // 132096

// SW128 swizzle of a byte offset within a (rows x 128B) tile
__device__ __forceinline__ uint32_t sw128(uint32_t off) {
    return off ^ ((off >> 3) & 0x70);
}

template <bool DO_BIAS, bool DO_RELU, bool DO_RESID>
__global__ __launch_bounds__(288) void gemm_tf32_kernel(
    const __grid_constant__ CUtensorMap tmA,
    const __grid_constant__ CUtensorMap tmB,
    const float* __restrict__ bias,
    const float* __restrict__ resid,
    float*       __restrict__ C,
    int N, int K)
{
    extern __shared__ __align__(1024) char smem[];
    const uint32_t sb = smem_u32(smem);
    const int tid  = threadIdx.x;
    const int wid  = tid >> 5;
    const int lane = tid & 31;
    const int m0 = blockIdx.y * GBM;
    const int n0 = blockIdx.x * GBN;

    // barriers: full[s] at sb + 8s ; empty[s] at sb + 64 + 8s
    if (tid == 0) {
        #pragma unroll
        for (int s = 0; s < GS; s++) {
            MBARRIER_INIT(sb + 8 * s, 1);        // full: TMA tx-based
            MBARRIER_INIT(sb + 64 + 8 * s, 8);   // empty: 8 consumer warps
        }
    }
    __syncthreads();

    const int nk = K / GBK;

    if (wid == 8) {
        // ---------------- producer warp (lane 0) ----------------
        if (lane == 0) {
            for (int j = 0; j < nk; j++) {
                const int s = j & (GS - 1);
                const int w = j >> 2;
                if (w > 0) MBARRIER_WAIT_PARITY_RELAXED(sb + 64 + 8 * s, (w - 1) & 1);
                MBARRIER_EXPECT_TX(sb + 8 * s, STAGE_BYTES);
                TMA2D(sb + SMEM_A_OFF(s), &tmA, j * GBK, m0, sb + 8 * s);
                TMA2D(sb + SMEM_B_OFF(s), &tmB, j * GBK, n0, sb + 8 * s);
            }
        }
        return;
    }

    // ---------------- consumer warps (0..7): warp tile 64(m) x 32(n) -------
    const int warp_m = wid >> 2;   // 0..1
    const int warp_n = wid & 3;    // 0..3
    const int g   = lane >> 2;     // 0..7
    const int tig = lane & 3;      // 0..3

    float acc[4][4][4];
    #pragma unroll
    for (int i = 0; i < 4; i++)
        #pragma unroll
        for (int j = 0; j < 4; j++)
            #pragma unroll
            for (int q = 0; q < 4; q++) acc[i][j][q] = 0.f;

    // precompute per-thread row byte offsets + swizzle xor terms
    uint32_t aRowOff[4], aRowXor[4];   // for rows (base) ; +8 row handled via +1024^ xor
    #pragma unroll
    for (int mf = 0; mf < 4; mf++) {
        const int row = warp_m * 64 + mf * 16 + g;
        aRowOff[mf] = (uint32_t)row * 128;
        aRowXor[mf] = ((uint32_t)row & 7) << 4;
    }
    uint32_t bRowOff[4], bRowXor[4];
    #pragma unroll
    for (int nf = 0; nf < 4; nf++) {
        const int row = warp_n * 32 + nf * 8 + g;
        bRowOff[nf] = (uint32_t)row * 128;
        bRowXor[nf] = ((uint32_t)row & 7) << 4;
    }

    for (int i = 0; i < nk; i++) {
        const int s  = i & (GS - 1);
        const int ph = (i >> 2) & 1;
        MBARRIER_WAIT_PARITY(sb + 8 * s, ph);

        const uint32_t aB = sb + SMEM_A_OFF(s);
        const uint32_t bB = sb + SMEM_B_OFF(s);

        #pragma unroll
        for (int kf = 0; kf < 4; kf++) {
            const uint32_t k0b = (uint32_t)(kf * 8 + tig) * 4;   // k byte
            const uint32_t k1b = k0b + 16;                       // k+4 byte
            float a[4][4];
            #pragma unroll
            for (int mf = 0; mf < 4; mf++) {
                // row and row+8: row+8 flips nothing in (&7) (16-stride tiles keep g in row low bits)
                // row+8: off += 8*128 = 1024 ; (row+8)&7 == row&7 since row%16 = g (g<8)
                a[mf][0] = lds_f32(aB + aRowOff[mf] + (k0b ^ aRowXor[mf]));
                a[mf][1] = lds_f32(aB + aRowOff[mf] + 1024 + (k0b ^ aRowXor[mf]));
                a[mf][2] = lds_f32(aB + aRowOff[mf] + (k1b ^ aRowXor[mf]));
                a[mf][3] = lds_f32(aB + aRowOff[mf] + 1024 + (k1b ^ aRowXor[mf]));
            }
            float b[4][2];
            #pragma unroll
            for (int nf = 0; nf < 4; nf++) {
                b[nf][0] = lds_f32(bB + bRowOff[nf] + (k0b ^ bRowXor[nf]));
                b[nf][1] = lds_f32(bB + bRowOff[nf] + (k1b ^ bRowXor[nf]));
            }
            #pragma unroll
            for (int mf = 0; mf < 4; mf++)
                #pragma unroll
                for (int nf = 0; nf < 4; nf++)
                    mma_tf32(acc[mf][nf], a[mf], b[nf]);
        }

        __syncwarp();
        if (lane == 0) MBARRIER_ARRIVE(sb + 64 + 8 * s);
    }

    // ---------------- epilogue ----------------
    #pragma unroll
    for (int mf = 0; mf < 4; mf++) {
        const int row0 = m0 + warp_m * 64 + mf * 16 + g;
        #pragma unroll
        for (int nf = 0; nf < 4; nf++) {
            const int col = n0 + warp_n * 32 + nf * 8 + 2 * tig;
            float2 v0 = make_float2(acc[mf][nf][0], acc[mf][nf][1]);
            float2 v1 = make_float2(acc[mf][nf][2], acc[mf][nf][3]);
            if (DO_BIAS) {
                float2 bb = *(const float2*)(bias + col);
                v0.x += bb.x; v0.y += bb.y; v1.x += bb.x; v1.y += bb.y;
            }
            if (DO_RELU) {
                v0.x = fmaxf(v0.x, 0.f); v0.y = fmaxf(v0.y, 0.f);
                v1.x = fmaxf(v1.x, 0.f); v1.y = fmaxf(v1.y, 0.f);
            }
            if (DO_RESID) {
                float2 r0 = *(const float2*)(resid + (size_t)row0 * N + col);
                float2 r1 = *(const float2*)(resid + (size_t)(row0 + 8) * N + col);
                v0.x += r0.x; v0.y += r0.y; v1.x += r1.x; v1.y += r1.y;
            }
            *(float2*)(C + (size_t)row0 * N + col)       = v0;
            *(float2*)(C + (size_t)(row0 + 8) * N + col) = v1;
        }
    }
}

// ====================== transpose [R,C] -> [C,R] ===========================
__global__ __launch_bounds__(256) void transpose_kernel(
    const float* __restrict__ in, float* __restrict__ out, int R, int C)
{
    __shared__ float t[32][33];
    const int bx = blockIdx.x * 32, by = blockIdx.y * 32;
    const int x = threadIdx.x, y = threadIdx.y;
    #pragma unroll
    for (int i = 0; i < 32; i += 8)
        t[y + i][x] = in[(size_t)(by + y + i) * C + bx + x];
    __syncthreads();
    #pragma unroll
    for (int i = 0; i < 32; i += 8)
        out[(size_t)(bx + y + i) * R + by + x] = t[x][y + i];
}

// ====================== LayerNorm ==========================================
template <bool FUSE_ADD>
__global__ __launch_bounds__(256) void ln_kernel(
    const float* __restrict__ x,
    const float* __restrict__ addend,
    float*       __restrict__ resid_out,
    const float* __restrict__ gamma,
    const float* __restrict__ beta,
    float*       __restrict__ out)
{
    const int row = blockIdx.x;
    const int t   = threadIdx.x;
    const size_t base = (size_t)row * EMB;

    float4 v = *(const float4*)(x + base + t * 4);
    if (FUSE_ADD) {
        float4 a = *(const float4*)(addend + base + t * 4);
        v.x += a.x; v.y += a.y; v.z += a.z; v.w += a.w;
        *(float4*)(resid_out + base + t * 4) = v;
    }
    float s  = v.x + v.y + v.z + v.w;
    float ss = v.x*v.x + v.y*v.y + v.z*v.z + v.w*v.w;

    #pragma unroll
    for (int off = 16; off; off >>= 1) {
        s  += __shfl_down_sync(0xffffffffu, s,  off);
        ss += __shfl_down_sync(0xffffffffu, ss, off);
    }
    __shared__ float rs[8], rss[8];
    const int warp = t >> 5, lane = t & 31;
    if (lane == 0) { rs[warp] = s; rss[warp] = ss; }
    __syncthreads();
    if (t == 0) {
        float a = 0.f, b = 0.f;
        #pragma unroll
        for (int i = 0; i < 8; i++) { a += rs[i]; b += rss[i]; }
        rs[0] = a; rss[0] = b;
    }
    __syncthreads();
    const float mu  = rs[0] * (1.0f / EMB);
    const float var = rss[0] * (1.0f / EMB) - mu * mu;
    const float inv = rsqrtf(var + 1e-5f);

    float4 g  = *(const float4*)(gamma + t * 4);
    float4 b4 = *(const float4*)(beta  + t * 4);
    float4 o;
    o.x = (v.x - mu) * inv * g.x + b4.x;
    o.y = (v.y - mu) * inv * g.y + b4.y;
    o.z = (v.z - mu) * inv * g.z + b4.z;
    o.w = (v.w - mu) * inv * g.w + b4.w;
    *(float4*)(out + base + t * 4) = o;
}

// ====================== Flash attention (ALiBi, causal) ====================
__global__ __launch_bounds__(128) void attn_kernel(
    const float* __restrict__ kqv, float* __restrict__ out)
{
    const int b = blockIdx.z;
    const int h = blockIdx.y;
    const int q = blockIdx.x * 128 + threadIdx.x;
    const int tid = threadIdx.x;
    const float slope = exp2f(-0.5f * (float)(h + 1));

    __shared__ float Ks[64][64];
    __shared__ float Vs[64][64];

    float4 qr[16];
    {
        const float* qp = kqv + ((size_t)(b * SEQ + q)) * (3 * EMB) + EMB + h * HD;
        #pragma unroll
        for (int i = 0; i < 16; i++) qr[i] = *(const float4*)(qp + i * 4);
    }

    float4 o[16];
    #pragma unroll
    for (int i = 0; i < 16; i++) o[i] = make_float4(0.f, 0.f, 0.f, 0.f);
    float m = -INFINITY, l = 0.f;

    const int ntiles = blockIdx.x * 2 + 2;
    for (int t = 0; t < ntiles; t++) {
        __syncthreads();
        #pragma unroll
        for (int i = 0; i < 8; i++) {
            const int idx = tid + i * 128;
            const int j   = idx >> 4;
            const int d4  = idx & 15;
            const float* kp = kqv + ((size_t)(b * SEQ + t * 64 + j)) * (3 * EMB) + h * HD;
            *(float4*)&Ks[j][d4 * 4] = *(const float4*)(kp + d4 * 4);
            *(float4*)&Vs[j][d4 * 4] = *(const float4*)(kp + 2 * EMB + d4 * 4);
        }
        __syncthreads();

        const int jmax = min(64, q - t * 64 + 1);
        for (int j = 0; j < jmax; j++) {
            float s = 0.f;
            #pragma unroll
            for (int d4 = 0; d4 < 16; d4++) {
                float4 kv = *(float4*)&Ks[j][d4 * 4];
                s += qr[d4].x * kv.x + qr[d4].y * kv.y
                   + qr[d4].z * kv.z + qr[d4].w * kv.w;
            }
            const int key = t * 64 + j;
            s = s * (1.0f / 32.0f) + slope * (float)(key - q);

            float p;
            if (s > m) {
                const float c = __expf(m - s);
                l *= c;
                #pragma unroll
                for (int d4 = 0; d4 < 16; d4++) {
                    o[d4].x *= c; o[d4].y *= c; o[d4].z *= c; o[d4].w *= c;
                }
                m = s; p = 1.f;
            } else {
                p = __expf(s - m);
            }
            l += p;
            #pragma unroll
            for (int d4 = 0; d4 < 16; d4++) {
                float4 vv = *(float4*)&Vs[j][d4 * 4];
                o[d4].x += p * vv.x; o[d4].y += p * vv.y;
                o[d4].z += p * vv.z; o[d4].w += p * vv.w;
            }
        }
    }

    const float inv = 1.0f / l;
    float* op = out + ((size_t)(b * SEQ + q)) * EMB + h * HD;
    #pragma unroll
    for (int d4 = 0; d4 < 16; d4++) {
        float4 v = o[d4];
        v.x *= inv; v.y *= inv; v.z *= inv; v.w *= inv;
        *(float4*)(op + d4 * 4) = v;
    }
}

// ====================== host: tensor maps ==================================
typedef CUresult (*EncodeTiledFn)(
    CUtensorMap*, CUtensorMapDataType, cuuint32_t, void*,
    const cuuint64_t*, const cuuint64_t*, const cuuint32_t*, const cuuint32_t*,
    CUtensorMapInterleave, CUtensorMapSwizzle, CUtensorMapL2promotion,
    CUtensorMapFloatOOBfill);

static void make_map(EncodeTiledFn enc, CUtensorMap* m, const float* p,
                     int K, int rows, int boxRows) {
    cuuint64_t dims[2]    = {(cuuint64_t)K, (cuuint64_t)rows};
    cuuint64_t strides[1] = {(cuuint64_t)K * 4};
    cuuint32_t box[2]     = {(cuuint32_t)GBK, (cuuint32_t)boxRows};
    cuuint32_t es[2]      = {1, 1};
    enc(m, CU_TENSOR_MAP_DATA_TYPE_FLOAT32, 2, (void*)p, dims, strides, box, es,
        CU_TENSOR_MAP_INTERLEAVE_NONE, CU_TENSOR_MAP_SWIZZLE_128B,
        CU_TENSOR_MAP_L2_PROMOTION_L2_128B, CU_TENSOR_MAP_FLOAT_OOB_FILL_NONE);
}

// ====================== driver =============================================
extern "C" void kernel_launch(void* const* d_in, const int* in_sizes, int n_in,
                              void* d_out, int out_size)
{
    const float* x     = (const float*)d_in[0];
    const float* w_kqv = (const float*)d_in[1];
    const float* ln1_g = (const float*)d_in[2];
    const float* ln1_b = (const float*)d_in[3];
    const float* ln2_g = (const float*)d_in[4];
    const float* ln2_b = (const float*)d_in[5];
    const float* w1    = (const float*)d_in[6];
    const float* b1    = (const float*)d_in[7];
    const float* w2    = (const float*)d_in[8];
    const float* b2    = (const float*)d_in[9];
    float* out = (float*)d_out;

    float *xn, *kqv, *attn, *hbuf, *mid, *wkqvT, *w1T, *w2T;
    cudaGetSymbolAddress((void**)&xn,    g_xn);
    cudaGetSymbolAddress((void**)&kqv,   g_kqv);
    cudaGetSymbolAddress((void**)&attn,  g_attn);
    cudaGetSymbolAddress((void**)&hbuf,  g_h);
    cudaGetSymbolAddress((void**)&mid,   g_mid);
    cudaGetSymbolAddress((void**)&wkqvT, g_wkqvT);
    cudaGetSymbolAddress((void**)&w1T,   g_w1T);
    cudaGetSymbolAddress((void**)&w2T,   g_w2T);

    EncodeTiledFn enc = nullptr;
    {
        cudaDriverEntryPointQueryResult st;
        cudaGetDriverEntryPointByVersion("cuTensorMapEncodeTiled", (void**)&enc,
                                         12000, cudaEnableDefault, &st);
    }

    alignas(64) CUtensorMap mA1, mB1, mA2, mB2, mA3, mB3;
    make_map(enc, &mA1, xn,    EMB, ROWS,    GBM);
    make_map(enc, &mB1, wkqvT, EMB, 3 * EMB, GBN);
    make_map(enc, &mA2, hbuf,  EMB, ROWS,    GBM);
    make_map(enc, &mB2, w1T,   EMB, DFF,     GBN);
    make_map(enc, &mA3, mid,   DFF, ROWS,    GBM);
    make_map(enc, &mB3, w2T,   DFF, EMB,     GBN);

    cudaFuncSetAttribute(gemm_tf32_kernel<false, false, false>,
                         cudaFuncAttributeMaxDynamicSharedMemorySize, GEMM_SMEM_TOTAL);
    cudaFuncSetAttribute(gemm_tf32_kernel<true, true, false>,
                         cudaFuncAttributeMaxDynamicSharedMemorySize, GEMM_SMEM_TOTAL);
    cudaFuncSetAttribute(gemm_tf32_kernel<true, false, true>,
                         cudaFuncAttributeMaxDynamicSharedMemorySize, GEMM_SMEM_TOTAL);

    // 0) weight transposes: [K,N] -> [N,K]
    transpose_kernel<<<dim3(3 * EMB / 32, EMB / 32), dim3(32, 8)>>>(w_kqv, wkqvT, EMB, 3 * EMB);
    transpose_kernel<<<dim3(DFF / 32, EMB / 32), dim3(32, 8)>>>(w1, w1T, EMB, DFF);
    transpose_kernel<<<dim3(EMB / 32, DFF / 32), dim3(32, 8)>>>(w2, w2T, DFF, EMB);

    // 1) LN1
    ln_kernel<false><<<ROWS, 256>>>(x, nullptr, nullptr, ln1_g, ln1_b, xn);

    // 2) kqv = xn @ w_kqv
    gemm_tf32_kernel<false, false, false>
        <<<dim3(3 * EMB / GBN, ROWS / GBM), 288, GEMM_SMEM_TOTAL>>>(
            mA1, mB1, nullptr, nullptr, kqv, 3 * EMB, EMB);

    // 3) attention
    attn_kernel<<<dim3(SEQ / 128, NH, BATCH), 128>>>(kqv, attn);

    // 4) x1 = x + attn (-> out), h = LN2(x1)
    ln_kernel<true><<<ROWS, 256>>>(x, attn, out, ln2_g, ln2_b, hbuf);

    // 5) mid = relu(h @ w1 + b1)
    gemm_tf32_kernel<true, true, false>
        <<<dim3(DFF / GBN, ROWS / GBM), 288, GEMM_SMEM_TOTAL>>>(
            mA2, mB2, b1, nullptr, mid, DFF, EMB);

    // 6) out = x1 + mid @ w2 + b2
    gemm_tf32_kernel<true, false, true>
        <<<dim3(EMB / GBN, ROWS / GBM), 288, GEMM_SMEM_TOTAL>>>(
            mA3, mB3, b2, out, out, EMB, DFF);

    (void)in_sizes; (void)n_in; (void)out_size;
}

// round 4
// speedup vs baseline: 4.6189x; 2.3595x over previous
#include <cuda_runtime.h>
#include <cuda.h>
#include <stdint.h>
#include <math.h>

#define BATCH 2
#define SEQ   2048
#define EMB   1024
#define NH    16
#define HD    64
#define DFF   4096
#define ROWS  (BATCH*SEQ)   // 4096

// ---------------- scratch (device globals; no allocation) ----------------
__device__ __align__(128) float g_xn   [ROWS * EMB];
__device__ __align__(128) float g_kqv  [ROWS * 3 * EMB];
__device__ __align__(128) float g_attn [ROWS * EMB];
__device__ __align__(128) float g_h    [ROWS * EMB];
__device__ __align__(128) float g_mid  [ROWS * DFF];
__device__ __align__(128) float g_wkqvT[3 * EMB * EMB];   // [3E, E]  (N,K)
__device__ __align__(128) float g_w1T  [DFF * EMB];       // [DFF, E]
__device__ __align__(128) float g_w2T  [EMB * DFF];       // [E, DFF]

// ====================== PTX helpers ========================================
__device__ __forceinline__ uint32_t smem_u32(const void* p) {
    uint32_t a;
    asm("{ .reg .u64 t; cvta.to.shared.u64 t, %1; cvt.u32.u64 %0, t; }"
        : "=r"(a) : "l"(p));
    return a;
}

__device__ __forceinline__ float tf32r(float x) {   // round-to-nearest tf32
    uint32_t u;
    asm("cvt.rna.tf32.f32 %0, %1;" : "=r"(u) : "f"(x));
    return __uint_as_float(u);
}

__device__ __forceinline__ float ex2(float x) {     // 2^x approx (MUFU)
    float y;
    asm("ex2.approx.f32 %0, %1;" : "=f"(y) : "f"(x));
    return y;
}

#define MBARRIER_INIT(addr, cnt) \
    asm volatile("mbarrier.init.shared.b64 [%0], %1;" :: "r"((uint32_t)(addr)), "r"((uint32_t)(cnt)) : "memory")

#define MBARRIER_ARRIVE(addr) \
    asm volatile("mbarrier.arrive.shared.b64 _, [%0];" :: "r"((uint32_t)(addr)) : "memory")

#define MBARRIER_EXPECT_TX(addr, bytes) \
    asm volatile("mbarrier.arrive.expect_tx.shared.b64 _, [%0], %1;" :: "r"((uint32_t)(addr)), "r"((uint32_t)(bytes)) : "memory")

#define MBARRIER_WAIT_PARITY(addr, ph) do { \
    uint32_t _m = (uint32_t)(addr); uint32_t _p = (uint32_t)(ph); uint32_t _d; \
    asm volatile("{\n\t.reg .pred p;\n\t" \
        "mbarrier.try_wait.parity.acquire.cta.shared::cta.b64 p, [%1], %2;\n\t" \
        "selp.b32 %0, 1, 0, p;\n\t}" : "=r"(_d) : "r"(_m), "r"(_p) : "memory"); \
    if (!_d) { \
        asm volatile("{\n\t.reg .pred P1;\n\t" \
            "WL_%=:\n\t" \
            "mbarrier.try_wait.parity.acquire.cta.shared::cta.b64 P1, [%0], %1, 0x989680;\n\t" \
            "@P1 bra.uni WD_%=;\n\t" \
            "bra.uni WL_%=;\n\t" \
            "WD_%=:\n\t}" :: "r"(_m), "r"(_p) : "memory"); \
    } \
} while (0)

#define MBARRIER_WAIT_PARITY_RELAXED(addr, ph) do { \
    uint32_t _m = (uint32_t)(addr); uint32_t _p = (uint32_t)(ph); uint32_t _d; \
    asm volatile("{\n\t.reg .pred p;\n\t" \
        "mbarrier.try_wait.parity.relaxed.cta.shared::cta.b64 p, [%1], %2, 0x989680;\n\t" \
        "selp.b32 %0, 1, 0, p;\n\t}" : "=r"(_d) : "r"(_m), "r"(_p) : "memory"); \
    if (!_d) { \
        asm volatile("{\n\t.reg .pred P1;\n\t" \
            "WL_%=:\n\t" \
            "mbarrier.try_wait.parity.relaxed.cta.shared::cta.b64 P1, [%0], %1, 0x989680;\n\t" \
            "@P1 bra.uni WD_%=;\n\t" \
            "bra.uni WL_%=;\n\t" \
            "WD_%=:\n\t}" :: "r"(_m), "r"(_p) : "memory"); \
    } \
} while (0)

#define TMA2D(smemaddr, mapptr, cx, cy, mbar) \
    asm volatile("cp.async.bulk.tensor.2d.shared::cta.global.tile.mbarrier::complete_tx::bytes " \
        "[%0], [%1, {%2, %3}], [%4];" \
        :: "r"((uint32_t)(smemaddr)), "l"(mapptr), "r"((int)(cx)), "r"((int)(cy)), \
           "r"((uint32_t)(mbar)) : "memory")

__device__ __forceinline__ float lds_f32(uint32_t addr) {
    float v;
    asm volatile("ld.shared.f32 %0, [%1];" : "=f"(v) : "r"(addr));
    return v;
}

__device__ __forceinline__ void cpasync16(uint32_t dst, const void* src) {
    asm volatile("cp.async.cg.shared.global [%0], [%1], 16;" :: "r"(dst), "l"(src));
}
#define CP_COMMIT() asm volatile("cp.async.commit_group;" ::: "memory")
#define CP_WAIT(n)  asm volatile("cp.async.wait_group %0;" :: "n"(n) : "memory")

// mma.sync m16n8k8 tf32 (legacy tensor-core path; valid PTX for sm_103 generic)
__device__ __forceinline__ void mma_tf32(float* c, const float* a, const float* b) {
    asm volatile(
        "mma.sync.aligned.m16n8k8.row.col.f32.tf32.tf32.f32 "
        "{%0,%1,%2,%3}, {%4,%5,%6,%7}, {%8,%9}, {%0,%1,%2,%3};"
        : "+f"(c[0]), "+f"(c[1]), "+f"(c[2]), "+f"(c[3])
        : "r"(__float_as_uint(a[0])), "r"(__float_as_uint(a[1])),
          "r"(__float_as_uint(a[2])), "r"(__float_as_uint(a[3])),
          "r"(__float_as_uint(b[0])), "r"(__float_as_uint(b[1])));
}

// ====================== GEMM (TMA + mma.sync tf32) =========================
#define GBM 128
#define GBN 128
#define GBK 32
#define GS  4
#define STAGE_A_BYTES (GBM * GBK * 4)
#define STAGE_B_BYTES (GBN * GBK * 4)
#define STAGE_BYTES   (STAGE_A_BYTES + STAGE_B_BYTES)
#define SMEM_A_OFF(s) (1024 + (s) * STAGE_BYTES)
#define SMEM_B_OFF(s) (SMEM_A_OFF(s) + STAGE_A_BYTES)
#define GEMM_SMEM_TOTAL (1024 + GS * STAGE_BYTES)

template <bool DO_BIAS, bool DO_RELU, bool DO_RESID, bool DO_TF32OUT>
__global__ __launch_bounds__(288) void gemm_tf32_kernel(
    const __grid_constant__ CUtensorMap tmA,
    const __grid_constant__ CUtensorMap tmB,
    const float* __restrict__ bias,
    const float* __restrict__ resid,
    float*       __restrict__ C,
    int N, int K)
{
    extern __shared__ __align__(1024) char smem[];
    const uint32_t sb = smem_u32(smem);
    const int tid  = threadIdx.x;
    const int wid  = tid >> 5;
    const int lane = tid & 31;
    const int m0 = blockIdx.y * GBM;
    const int n0 = blockIdx.x * GBN;

    if (tid == 0) {
        #pragma unroll
        for (int s = 0; s < GS; s++) {
            MBARRIER_INIT(sb + 8 * s, 1);
            MBARRIER_INIT(sb + 64 + 8 * s, 8);
        }
    }
    __syncthreads();

    const int nk = K / GBK;

    if (wid == 8) {
        if (lane == 0) {
            for (int j = 0; j < nk; j++) {
                const int s = j & (GS - 1);
                const int w = j >> 2;
                if (w > 0) MBARRIER_WAIT_PARITY_RELAXED(sb + 64 + 8 * s, (w - 1) & 1);
                MBARRIER_EXPECT_TX(sb + 8 * s, STAGE_BYTES);
                TMA2D(sb + SMEM_A_OFF(s), &tmA, j * GBK, m0, sb + 8 * s);
                TMA2D(sb + SMEM_B_OFF(s), &tmB, j * GBK, n0, sb + 8 * s);
            }
        }
        return;
    }

    const int warp_m = wid >> 2;
    const int warp_n = wid & 3;
    const int g   = lane >> 2;
    const int tig = lane & 3;

    float acc[4][4][4];
    #pragma unroll
    for (int i = 0; i < 4; i++)
        #pragma unroll
        for (int j = 0; j < 4; j++)
            #pragma unroll
            for (int q = 0; q < 4; q++) acc[i][j][q] = 0.f;

    uint32_t aRowOff[4], aRowXor[4];
    #pragma unroll
    for (int mf = 0; mf < 4; mf++) {
        const int row = warp_m * 64 + mf * 16 + g;
        aRowOff[mf] = (uint32_t)row * 128;
        aRowXor[mf] = ((uint32_t)row & 7) << 4;
    }
    uint32_t bRowOff[4], bRowXor[4];
    #pragma unroll
    for (int nf = 0; nf < 4; nf++) {
        const int row = warp_n * 32 + nf * 8 + g;
        bRowOff[nf] = (uint32_t)row * 128;
        bRowXor[nf] = ((uint32_t)row & 7) << 4;
    }

    for (int i = 0; i < nk; i++) {
        const int s  = i & (GS - 1);
        const int ph = (i >> 2) & 1;
        MBARRIER_WAIT_PARITY(sb + 8 * s, ph);

        const uint32_t aB = sb + SMEM_A_OFF(s);
        const uint32_t bB = sb + SMEM_B_OFF(s);

        #pragma unroll
        for (int kf = 0; kf < 4; kf++) {
            const uint32_t k0b = (uint32_t)(kf * 8 + tig) * 4;
            const uint32_t k1b = k0b + 16;
            float a[4][4];
            #pragma unroll
            for (int mf = 0; mf < 4; mf++) {
                a[mf][0] = lds_f32(aB + aRowOff[mf] + (k0b ^ aRowXor[mf]));
                a[mf][1] = lds_f32(aB + aRowOff[mf] + 1024 + (k0b ^ aRowXor[mf]));
                a[mf][2] = lds_f32(aB + aRowOff[mf] + (k1b ^ aRowXor[mf]));
                a[mf][3] = lds_f32(aB + aRowOff[mf] + 1024 + (k1b ^ aRowXor[mf]));
            }
            float b[4][2];
            #pragma unroll
            for (int nf = 0; nf < 4; nf++) {
                b[nf][0] = lds_f32(bB + bRowOff[nf] + (k0b ^ bRowXor[nf]));
                b[nf][1] = lds_f32(bB + bRowOff[nf] + (k1b ^ bRowXor[nf]));
            }
            #pragma unroll
            for (int mf = 0; mf < 4; mf++)
                #pragma unroll
                for (int nf = 0; nf < 4; nf++)
                    mma_tf32(acc[mf][nf], a[mf], b[nf]);
        }

        __syncwarp();
        if (lane == 0) MBARRIER_ARRIVE(sb + 64 + 8 * s);
    }

    #pragma unroll
    for (int mf = 0; mf < 4; mf++) {
        const int row0 = m0 + warp_m * 64 + mf * 16 + g;
        #pragma unroll
        for (int nf = 0; nf < 4; nf++) {
            const int col = n0 + warp_n * 32 + nf * 8 + 2 * tig;
            float2 v0 = make_float2(acc[mf][nf][0], acc[mf][nf][1]);
            float2 v1 = make_float2(acc[mf][nf][2], acc[mf][nf][3]);
            if (DO_BIAS) {
                float2 bb = *(const float2*)(bias + col);
                v0.x += bb.x; v0.y += bb.y; v1.x += bb.x; v1.y += bb.y;
            }
            if (DO_RELU) {
                v0.x = fmaxf(v0.x, 0.f); v0.y = fmaxf(v0.y, 0.f);
                v1.x = fmaxf(v1.x, 0.f); v1.y = fmaxf(v1.y, 0.f);
            }
            if (DO_TF32OUT) {
                v0.x = tf32r(v0.x); v0.y = tf32r(v0.y);
                v1.x = tf32r(v1.x); v1.y = tf32r(v1.y);
            }
            if (DO_RESID) {
                float2 r0 = *(const float2*)(resid + (size_t)row0 * N + col);
                float2 r1 = *(const float2*)(resid + (size_t)(row0 + 8) * N + col);
                v0.x += r0.x; v0.y += r0.y; v1.x += r1.x; v1.y += r1.y;
            }
            *(float2*)(C + (size_t)row0 * N + col)       = v0;
            *(float2*)(C + (size_t)(row0 + 8) * N + col) = v1;
        }
    }
}

// ====================== transpose [R,C] -> [C,R] (rounds to tf32) ==========
__global__ __launch_bounds__(256) void transpose_kernel(
    const float* __restrict__ in, float* __restrict__ out, int R, int C)
{
    __shared__ float t[32][33];
    const int bx = blockIdx.x * 32, by = blockIdx.y * 32;
    const int x = threadIdx.x, y = threadIdx.y;
    #pragma unroll
    for (int i = 0; i < 32; i += 8)
        t[y + i][x] = tf32r(in[(size_t)(by + y + i) * C + bx + x]);
    __syncthreads();
    #pragma unroll
    for (int i = 0; i < 32; i += 8)
        out[(size_t)(bx + y + i) * R + by + x] = t[x][y + i];
}

// ====================== LayerNorm (output rounded to tf32) =================
template <bool FUSE_ADD>
__global__ __launch_bounds__(256) void ln_kernel(
    const float* __restrict__ x,
    const float* __restrict__ addend,
    float*       __restrict__ resid_out,
    const float* __restrict__ gamma,
    const float* __restrict__ beta,
    float*       __restrict__ out)
{
    const int row = blockIdx.x;
    const int t   = threadIdx.x;
    const size_t base = (size_t)row * EMB;

    float4 v = *(const float4*)(x + base + t * 4);
    if (FUSE_ADD) {
        float4 a = *(const float4*)(addend + base + t * 4);
        v.x += a.x; v.y += a.y; v.z += a.z; v.w += a.w;
        *(float4*)(resid_out + base + t * 4) = v;
    }
    float s  = v.x + v.y + v.z + v.w;
    float ss = v.x*v.x + v.y*v.y + v.z*v.z + v.w*v.w;

    #pragma unroll
    for (int off = 16; off; off >>= 1) {
        s  += __shfl_down_sync(0xffffffffu, s,  off);
        ss += __shfl_down_sync(0xffffffffu, ss, off);
    }
    __shared__ float rs[8], rss[8];
    const int warp = t >> 5, lane = t & 31;
    if (lane == 0) { rs[warp] = s; rss[warp] = ss; }
    __syncthreads();
    if (t == 0) {
        float a = 0.f, b = 0.f;
        #pragma unroll
        for (int i = 0; i < 8; i++) { a += rs[i]; b += rss[i]; }
        rs[0] = a; rss[0] = b;
    }
    __syncthreads();
    const float mu  = rs[0] * (1.0f / EMB);
    const float var = rss[0] * (1.0f / EMB) - mu * mu;
    const float inv = rsqrtf(var + 1e-5f);

    float4 g  = *(const float4*)(gamma + t * 4);
    float4 b4 = *(const float4*)(beta  + t * 4);
    float4 o;
    o.x = tf32r((v.x - mu) * inv * g.x + b4.x);
    o.y = tf32r((v.y - mu) * inv * g.y + b4.y);
    o.z = tf32r((v.z - mu) * inv * g.z + b4.z);
    o.w = tf32r((v.w - mu) * inv * g.w + b4.w);
    *(float4*)(out + base + t * 4) = o;
}

// ====================== Flash attention (tensor cores) =====================
// grid (SEQ/64, NH, BATCH), block 128 (4 warps). Per block: 64 queries, 1 head.
// kqv row: [ k(0..1023) | q(1024..2047) | v(2048..3071) ]
// smem: Q[64][68] | K0[64][68] | K1[64][68] | V0[64][72] | V1[64][72]
#define AT_KOFF(s) (17408 + (s) * 17408)
#define AT_VOFF(s) (52224 + (s) * 18432)
#define ATTN_SMEM  89088

__device__ __forceinline__ void load_kv(uint32_t sb, const float* __restrict__ kqv,
                                        int b, int h, int t, int buf, int tid)
{
    const float* base = kqv + ((size_t)(b * SEQ + t * 64)) * 3072 + h * 64;
    const uint32_t kd = sb + AT_KOFF(buf);
    const uint32_t vd = sb + AT_VOFF(buf);
    #pragma unroll
    for (int i = 0; i < 8; i++) {
        const int idx = tid + i * 128;
        const int row = idx >> 4, c4 = idx & 15;
        cpasync16(kd + (uint32_t)(row * 68 + c4 * 4) * 4, base + (size_t)row * 3072 + c4 * 4);
        cpasync16(vd + (uint32_t)(row * 72 + c4 * 4) * 4, base + (size_t)row * 3072 + 2048 + c4 * 4);
    }
}

__global__ __launch_bounds__(128) void attn_kernel(
    const float* __restrict__ kqv, float* __restrict__ out)
{
    extern __shared__ __align__(16) char asmem[];
    const uint32_t sb = smem_u32(asmem);
    const int bx = blockIdx.x, h = blockIdx.y, b = blockIdx.z;
    const int tid = threadIdx.x, w = tid >> 5, lane = tid & 31;
    const int tig = lane & 3, grp = lane >> 2;
    const float LOG2E = 1.4426950408889634f;
    const float slope2 = exp2f(-0.5f * (float)(h + 1)) * LOG2E;
    const int q0 = bx * 64;
    const int nt = bx + 1;

    // prologue: Q + tile0 (+ tile1) via cp.async
    {
        const float* qb = kqv + ((size_t)(b * SEQ + q0)) * 3072 + 1024 + h * 64;
        #pragma unroll
        for (int i = 0; i < 8; i++) {
            const int idx = tid + i * 128, row = idx >> 4, c4 = idx & 15;
            cpasync16(sb + (uint32_t)(row * 68 + c4 * 4) * 4, qb + (size_t)row * 3072 + c4 * 4);
        }
    }
    load_kv(sb, kqv, b, h, 0, 0, tid);
    CP_COMMIT();
    if (nt > 1) { load_kv(sb, kqv, b, h, 1, 1, tid); CP_COMMIT(); CP_WAIT(1); }
    else        { CP_WAIT(0); }
    __syncthreads();

    // Q fragments, scale = log2(e)/sqrt(1024)
    const float* Qs = (const float*)asmem;
    float qa[8][4];
    {
        const int r0 = w * 16 + grp;
        const float qs = LOG2E / 32.0f;
        #pragma unroll
        for (int kk = 0; kk < 8; kk++) {
            const int c = kk * 8 + tig;
            qa[kk][0] = Qs[r0 * 68 + c] * qs;
            qa[kk][1] = Qs[(r0 + 8) * 68 + c] * qs;
            qa[kk][2] = Qs[r0 * 68 + c + 4] * qs;
            qa[kk][3] = Qs[(r0 + 8) * 68 + c + 4] * qs;
        }
    }

    float o[8][4];
    #pragma unroll
    for (int nf = 0; nf < 8; nf++) { o[nf][0] = o[nf][1] = o[nf][2] = o[nf][3] = 0.f; }
    float m0 = -INFINITY, m1 = -INFINITY, l0 = 0.f, l1 = 0.f;
    const int qrow = q0 + w * 16 + grp;

    for (int t = 0; t < nt; t++) {
        const float* Ks = (const float*)(asmem + AT_KOFF(t & 1));
        const float* Vs = (const float*)(asmem + AT_VOFF(t & 1));
        const bool diag = (t == nt - 1);

        // S = Q K^T (exp2 domain)
        float s[8][4];
        #pragma unroll
        for (int nf = 0; nf < 8; nf++) { s[nf][0] = s[nf][1] = s[nf][2] = s[nf][3] = 0.f; }
        #pragma unroll
        for (int kk = 0; kk < 8; kk++) {
            #pragma unroll
            for (int nf = 0; nf < 8; nf++) {
                float bf[2];
                bf[0] = Ks[(nf * 8 + grp) * 68 + kk * 8 + tig];
                bf[1] = Ks[(nf * 8 + grp) * 68 + kk * 8 + tig + 4];
                mma_tf32(s[nf], qa[kk], bf);
            }
        }

        // ALiBi bias + causal mask + tile max
        float mx0 = -INFINITY, mx1 = -INFINITY;
        #pragma unroll
        for (int nf = 0; nf < 8; nf++) {
            #pragma unroll
            for (int e = 0; e < 2; e++) {
                const int key = t * 64 + nf * 8 + 2 * tig + e;
                const float r0f = (float)(key - qrow);
                const float r1f = r0f - 8.0f;
                float v0 = s[nf][e]     + slope2 * r0f;
                float v1 = s[nf][e + 2] + slope2 * r1f;
                if (diag) {
                    if (r0f > 0.f) v0 = -1e30f;
                    if (r1f > 0.f) v1 = -1e30f;
                }
                s[nf][e] = v0; s[nf][e + 2] = v1;
                mx0 = fmaxf(mx0, v0); mx1 = fmaxf(mx1, v1);
            }
        }
        mx0 = fmaxf(mx0, __shfl_xor_sync(~0u, mx0, 1));
        mx0 = fmaxf(mx0, __shfl_xor_sync(~0u, mx0, 2));
        mx1 = fmaxf(mx1, __shfl_xor_sync(~0u, mx1, 1));
        mx1 = fmaxf(mx1, __shfl_xor_sync(~0u, mx1, 2));
        const float mn0 = fmaxf(m0, mx0), mn1 = fmaxf(m1, mx1);
        const float c0 = ex2(m0 - mn0), c1 = ex2(m1 - mn1);
        m0 = mn0; m1 = mn1;

        // P = exp2(S - m), row sums
        float rs0 = 0.f, rs1 = 0.f;
        #pragma unroll
        for (int nf = 0; nf < 8; nf++) {
            #pragma unroll
            for (int e = 0; e < 2; e++) {
                const float p0 = ex2(s[nf][e] - m0);
                const float p1 = ex2(s[nf][e + 2] - m1);
                s[nf][e] = p0; s[nf][e + 2] = p1;
                rs0 += p0; rs1 += p1;
            }
        }
        rs0 += __shfl_xor_sync(~0u, rs0, 1); rs0 += __shfl_xor_sync(~0u, rs0, 2);
        rs1 += __shfl_xor_sync(~0u, rs1, 1); rs1 += __shfl_xor_sync(~0u, rs1, 2);
        l0 = l0 * c0 + rs0; l1 = l1 * c1 + rs1;

        #pragma unroll
        for (int nf = 0; nf < 8; nf++) {
            o[nf][0] *= c0; o[nf][1] *= c0; o[nf][2] *= c1; o[nf][3] *= c1;
        }

        // O += P V  (P permuted C-layout -> A-layout via quad shfl)
        const int s1 = (lane & ~3) | (tig >> 1);
        const int s2 = s1 + 2;
        #pragma unroll
        for (int kk = 0; kk < 8; kk++) {
            const float v0 = __shfl_sync(~0u, s[kk][0], s1);
            const float v1 = __shfl_sync(~0u, s[kk][1], s1);
            const float v2 = __shfl_sync(~0u, s[kk][2], s1);
            const float v3 = __shfl_sync(~0u, s[kk][3], s1);
            const float w0 = __shfl_sync(~0u, s[kk][0], s2);
            const float w1 = __shfl_sync(~0u, s[kk][1], s2);
            const float w2 = __shfl_sync(~0u, s[kk][2], s2);
            const float w3 = __shfl_sync(~0u, s[kk][3], s2);
            float pa[4];
            pa[0] = (tig & 1) ? v1 : v0;
            pa[1] = (tig & 1) ? v3 : v2;
            pa[2] = (tig & 1) ? w1 : w0;
            pa[3] = (tig & 1) ? w3 : w2;
            #pragma unroll
            for (int nf = 0; nf < 8; nf++) {
                float bf[2];
                bf[0] = Vs[(kk * 8 + tig) * 72 + nf * 8 + grp];
                bf[1] = Vs[(kk * 8 + tig + 4) * 72 + nf * 8 + grp];
                mma_tf32(o[nf], pa, bf);
            }
        }

        __syncthreads();
        if (t + 1 < nt) {
            if (t + 2 < nt) { load_kv(sb, kqv, b, h, t + 2, t & 1, tid); CP_COMMIT(); CP_WAIT(1); }
            else            { CP_WAIT(0); }
            __syncthreads();
        }
    }

    const float il0 = 1.0f / l0, il1 = 1.0f / l1;
    float* op = out + ((size_t)(b * SEQ + qrow)) * EMB + h * 64;
    #pragma unroll
    for (int nf = 0; nf < 8; nf++) {
        const int col = nf * 8 + 2 * tig;
        float2 u0 = make_float2(o[nf][0] * il0, o[nf][1] * il0);
        float2 u1 = make_float2(o[nf][2] * il1, o[nf][3] * il1);
        *(float2*)(op + col) = u0;
        *(float2*)(op + (size_t)8 * EMB + col) = u1;
    }
}

// ====================== host: tensor maps ==================================
typedef CUresult (*EncodeTiledFn)(
    CUtensorMap*, CUtensorMapDataType, cuuint32_t, void*,
    const cuuint64_t*, const cuuint64_t*, const cuuint32_t*, const cuuint32_t*,
    CUtensorMapInterleave, CUtensorMapSwizzle, CUtensorMapL2promotion,
    CUtensorMapFloatOOBfill);

static void make_map(EncodeTiledFn enc, CUtensorMap* m, const float* p,
                     int K, int rows, int boxRows) {
    cuuint64_t dims[2]    = {(cuuint64_t)K, (cuuint64_t)rows};
    cuuint64_t strides[1] = {(cuuint64_t)K * 4};
    cuuint32_t box[2]     = {(cuuint32_t)GBK, (cuuint32_t)boxRows};
    cuuint32_t es[2]      = {1, 1};
    enc(m, CU_TENSOR_MAP_DATA_TYPE_FLOAT32, 2, (void*)p, dims, strides, box, es,
        CU_TENSOR_MAP_INTERLEAVE_NONE, CU_TENSOR_MAP_SWIZZLE_128B,
        CU_TENSOR_MAP_L2_PROMOTION_L2_128B, CU_TENSOR_MAP_FLOAT_OOB_FILL_NONE);
}

// ====================== driver =============================================
extern "C" void kernel_launch(void* const* d_in, const int* in_sizes, int n_in,
                              void* d_out, int out_size)
{
    const float* x     = (const float*)d_in[0];
    const float* w_kqv = (const float*)d_in[1];
    const float* ln1_g = (const float*)d_in[2];
    const float* ln1_b = (const float*)d_in[3];
    const float* ln2_g = (const float*)d_in[4];
    const float* ln2_b = (const float*)d_in[5];
    const float* w1    = (const float*)d_in[6];
    const float* b1    = (const float*)d_in[7];
    const float* w2    = (const float*)d_in[8];
    const float* b2    = (const float*)d_in[9];
    float* out = (float*)d_out;

    float *xn, *kqv, *attn, *hbuf, *mid, *wkqvT, *w1T, *w2T;
    cudaGetSymbolAddress((void**)&xn,    g_xn);
    cudaGetSymbolAddress((void**)&kqv,   g_kqv);
    cudaGetSymbolAddress((void**)&attn,  g_attn);
    cudaGetSymbolAddress((void**)&hbuf,  g_h);
    cudaGetSymbolAddress((void**)&mid,   g_mid);
    cudaGetSymbolAddress((void**)&wkqvT, g_wkqvT);
    cudaGetSymbolAddress((void**)&w1T,   g_w1T);
    cudaGetSymbolAddress((void**)&w2T,   g_w2T);

    EncodeTiledFn enc = nullptr;
    {
        cudaDriverEntryPointQueryResult st;
        cudaGetDriverEntryPointByVersion("cuTensorMapEncodeTiled", (void**)&enc,
                                         12000, cudaEnableDefault, &st);
    }

    alignas(64) CUtensorMap mA1, mB1, mA2, mB2, mA3, mB3;
    make_map(enc, &mA1, xn,    EMB, ROWS,    GBM);
    make_map(enc, &mB1, wkqvT, EMB, 3 * EMB, GBN);
    make_map(enc, &mA2, hbuf,  EMB, ROWS,    GBM);
    make_map(enc, &mB2, w1T,   EMB, DFF,     GBN);
    make_map(enc, &mA3, mid,   DFF, ROWS,    GBM);
    make_map(enc, &mB3, w2T,   DFF, EMB,     GBN);

    cudaFuncSetAttribute(gemm_tf32_kernel<false, false, false, true>,
                         cudaFuncAttributeMaxDynamicSharedMemorySize, GEMM_SMEM_TOTAL);
    cudaFuncSetAttribute(gemm_tf32_kernel<true, true, false, true>,
                         cudaFuncAttributeMaxDynamicSharedMemorySize, GEMM_SMEM_TOTAL);
    cudaFuncSetAttribute(gemm_tf32_kernel<true, false, true, false>,
                         cudaFuncAttributeMaxDynamicSharedMemorySize, GEMM_SMEM_TOTAL);
    cudaFuncSetAttribute(attn_kernel,
                         cudaFuncAttributeMaxDynamicSharedMemorySize, ATTN_SMEM);

    // 0) weight transposes (round to tf32)
    transpose_kernel<<<dim3(3 * EMB / 32, EMB / 32), dim3(32, 8)>>>(w_kqv, wkqvT, EMB, 3 * EMB);
    transpose_kernel<<<dim3(DFF / 32, EMB / 32), dim3(32, 8)>>>(w1, w1T, EMB, DFF);
    transpose_kernel<<<dim3(EMB / 32, DFF / 32), dim3(32, 8)>>>(w2, w2T, DFF, EMB);

    // 1) LN1
    ln_kernel<false><<<ROWS, 256>>>(x, nullptr, nullptr, ln1_g, ln1_b, xn);

    // 2) kqv = xn @ w_kqv  (output rounded to tf32 for attention mma)
    gemm_tf32_kernel<false, false, false, true>
        <<<dim3(3 * EMB / GBN, ROWS / GBM), 288, GEMM_SMEM_TOTAL>>>(
            mA1, mB1, nullptr, nullptr, kqv, 3 * EMB, EMB);

    // 3) attention (tensor cores)
    attn_kernel<<<dim3(SEQ / 64, NH, BATCH), 128, ATTN_SMEM>>>(kqv, attn);

    // 4) x1 = x + attn (-> out), h = LN2(x1)
    ln_kernel<true><<<ROWS, 256>>>(x, attn, out, ln2_g, ln2_b, hbuf);

    // 5) mid = relu(h @ w1 + b1)  (rounded to tf32)
    gemm_tf32_kernel<true, true, false, true>
        <<<dim3(DFF / GBN, ROWS / GBM), 288, GEMM_SMEM_TOTAL>>>(
            mA2, mB2, b1, nullptr, mid, DFF, EMB);

    // 6) out = x1 + mid @ w2 + b2
    gemm_tf32_kernel<true, false, true, false>
        <<<dim3(EMB / GBN, ROWS / GBM), 288, GEMM_SMEM_TOTAL>>>(
            mA3, mB3, b2, out, out, EMB, DFF);

    (void)in_sizes; (void)n_in; (void)out_size;
}